// round 13
// baseline (speedup 1.0000x reference)
#include <cuda_runtime.h>
#include <cuda_bf16.h>

// Problem dims (fixed by the dataset)
#define LSEQ 512
#define DIN  320
#define HID  512
#define G4   2048   // 4*H
#define MDIM 512
#define NBLK 64     // blocks per direction
#define UPB  8      // hidden units per block

// ---------------- scratch (static device globals; no allocation) ----------
__device__ float g_x0 [LSEQ * DIN];        // embeddings
__device__ float g_zf [LSEQ * G4];         // input-projection, forward dir
__device__ float g_zb [LSEQ * G4];         // input-projection, backward dir
__device__ float g_mlp[LSEQ * MDIM];       // per-node MLP
// layer outputs in "publish line" layout: [dir][t][blk][32 words]
//   floats 0..7 = h chunk, word 8 = flag, rest pad (one 128B line)
__device__ __align__(128) float g_pub1[2 * LSEQ * NBLK * 32];
__device__ __align__(128) float g_pub2[2 * LSEQ * NBLK * 32];

__device__ __forceinline__ float* bufsel(int id) {
    switch (id) {
        case 0: return g_x0;
        case 3: return g_zf;
        case 4: return g_zb;
        case 5: return g_mlp;
        case 6: return g_pub1;
        default: return g_pub2;
    }
}

__device__ __forceinline__ float tanh_f(float x) {
    float a = fabsf(x);
    float e = __expf(-2.0f * a);
    float r = __fdividef(1.0f - e, 1.0f + e);
    return copysignf(r, x);
}

__device__ __forceinline__ void st_release_u32(unsigned int* p, unsigned int v) {
    asm volatile("st.release.gpu.global.u32 [%0], %1;" :: "l"(p), "r"(v) : "memory");
}
__device__ __forceinline__ unsigned int ld_acquire_u32(const unsigned int* p) {
    unsigned int v;
    asm volatile("ld.acquire.gpu.global.u32 %0, [%1];" : "=r"(v) : "l"(p) : "memory");
    return v;
}
__device__ __forceinline__ uint4 ldcg_v4(const uint4* p) {
    uint4 v;
    asm volatile("ld.global.cg.v4.u32 {%0,%1,%2,%3}, [%4];"
                 : "=r"(v.x), "=r"(v.y), "=r"(v.z), "=r"(v.w) : "l"(p) : "memory");
    return v;
}

// ---- packed f32x2 helpers (fma.rn.f32x2 already proven in the scan) ------
typedef unsigned long long u64p;
#define ADD2(d,a,b)   asm("add.rn.f32x2 %0,%1,%2;"    : "=l"(d) : "l"(a), "l"(b))
#define MUL2(d,a,b)   asm("mul.rn.f32x2 %0,%1,%2;"    : "=l"(d) : "l"(a), "l"(b))
#define FMA2(d,a,b,c) asm("fma.rn.f32x2 %0,%1,%2,%3;" : "=l"(d) : "l"(a), "l"(b), "l"(c))
__device__ __forceinline__ u64p dup2(float x) {
    u64p r; asm("mov.b64 %0,{%1,%1};" : "=l"(r) : "f"(x)); return r;
}
__device__ __forceinline__ float rcp_f(float x) {
    float r; asm("rcp.approx.ftz.f32 %0,%1;" : "=f"(r) : "f"(x)); return r;
}

// ---------------- embedding gather ----------------------------------------
__global__ void embed_k(const int* __restrict__ wi, const int* __restrict__ pi,
                        const float* __restrict__ we, const float* __restrict__ pe)
{
    int t = blockIdx.x;
    int d = threadIdx.x;             // 320 threads
    float v;
    if (d < 256) v = we[(size_t)wi[t] * 256 + d];
    else         v = pe[(size_t)pi[t] * 64 + (d - 256)];
    g_x0[t * DIN + d] = v;
}

// ---------------- pub reset (every replay, before the scans) --------------
__global__ void zero_pub_k()
{
    int idx = blockIdx.x * blockDim.x + threadIdx.x;   // 2048*512 = 1048576
    uint4 z = make_uint4(0u, 0u, 0u, 0u);
    if (idx < 524288) ((uint4*)g_pub1)[idx] = z;       // each buf: 524288 uint4
    else              ((uint4*)g_pub2)[idx - 524288] = z;
}

// ---------------- f32 GEMM:  C[M,N] = A[M,K] * B[N,K]^T + b1 + b2 ---------
// amode=0: A dense [M][K].  amode=1: A in pub-line layout (K=1024,
// col c -> pub[c>>9][row][(c&511)>>3][c&7]).
__global__ void __launch_bounds__(256) gemm_tn(
    int aid, int amode,
    const float* __restrict__ B0, const float* __restrict__ b1_0,
    const float* __restrict__ b2_0, int cid0,
    const float* __restrict__ B1, const float* __restrict__ b1_1,
    const float* __restrict__ b2_1, int cid1,
    int M, int N, int K)
{
    const float* A  = bufsel(aid);
    const float* B  = blockIdx.z ? B1   : B0;
    const float* b1 = blockIdx.z ? b1_1 : b1_0;
    const float* b2 = blockIdx.z ? b2_1 : b2_0;
    float*       C  = bufsel(blockIdx.z ? cid1 : cid0);

    __shared__ float As[16][65];
    __shared__ float Bs[16][65];

    const int tid = threadIdx.x;
    const int tx  = tid & 15;
    const int ty  = tid >> 4;
    const int m0  = blockIdx.y * 64;
    const int n0  = blockIdx.x * 64;

    const int lr = tid >> 2;
    const int lk = (tid & 3) * 4;

    const float* Ap = A + (size_t)(m0 + lr) * K + lk;           // amode=0 path
    const float* Aprow = A + (size_t)(m0 + lr) * (NBLK * 32);   // amode=1 path
    const float* Bp = B + (size_t)(n0 + lr) * K + lk;

    float acc[4][4] = {};

    for (int k0 = 0; k0 < K; k0 += 16) {
        float4 av;
        if (amode) {
            int c  = k0 + lk;                 // global column 0..1023
            int d  = c >> 9;                  // direction
            int cc = c & 511;
            av = *(const float4*)(Aprow + (size_t)d * (LSEQ * NBLK * 32)
                                  + (cc >> 3) * 32 + (cc & 7));
        } else {
            av = *(const float4*)(Ap + k0);
        }
        float4 bv = *(const float4*)(Bp + k0);
        __syncthreads();
        As[lk + 0][lr] = av.x; As[lk + 1][lr] = av.y;
        As[lk + 2][lr] = av.z; As[lk + 3][lr] = av.w;
        Bs[lk + 0][lr] = bv.x; Bs[lk + 1][lr] = bv.y;
        Bs[lk + 2][lr] = bv.z; Bs[lk + 3][lr] = bv.w;
        __syncthreads();
#pragma unroll
        for (int kk = 0; kk < 16; kk++) {
            float a[4], b[4];
#pragma unroll
            for (int i = 0; i < 4; i++) a[i] = As[kk][ty + 16 * i];
#pragma unroll
            for (int j = 0; j < 4; j++) b[j] = Bs[kk][tx + 16 * j];
#pragma unroll
            for (int i = 0; i < 4; i++)
#pragma unroll
                for (int j = 0; j < 4; j++)
                    acc[i][j] += a[i] * b[j];
        }
    }

#pragma unroll
    for (int j = 0; j < 4; j++) {
        int n = n0 + tx + 16 * j;
        float bb = 0.0f;
        if (b1) bb += b1[n];
        if (b2) bb += b2[n];
#pragma unroll
        for (int i = 0; i < 4; i++) {
            C[(size_t)(m0 + ty + 16 * i) * N + n] = acc[i][j] + bb;
        }
    }
}

// ---------------- persistent bidirectional LSTM scan (R8, proven) ---------
__global__ void __launch_bounds__(256, 1) lstm_scan(
    const float* __restrict__ whf, const float* __restrict__ whb, int outid)
{
    const int dir = blockIdx.x >> 6;     // 0 fwd, 1 bwd
    const int blk = blockIdx.x & 63;
    const int tid = threadIdx.x;
    const int row = tid >> 3;            // 0..31 local row
    const int sub = tid & 7;             // 8 threads per row
    const int grow = (row >> 3) * HID + blk * UPB + (row & 7);

    const float* zin = dir ? g_zb : g_zf;
    const float* Whh = dir ? whb : whf;
    float* pub = bufsel(outid) + (size_t)dir * LSEQ * NBLK * 32;

    unsigned long long wp[32];
    const unsigned long long* w2 =
        (const unsigned long long*)(Whh + (size_t)grow * HID);
#pragma unroll
    for (int k = 0; k < 32; k++) wp[k] = w2[sub + 8 * k];

    __shared__ __align__(16) float hs[HID];
    __shared__ float zs[32];
    hs[tid] = 0.0f; hs[tid + 256] = 0.0f;
    float c = 0.0f;                      // live only on lanes 0..7 of warp 0
    __syncthreads();

    for (int t = 0; t < LSEQ; t++) {
        const int ta = dir ? (LSEQ - 1 - t) : t;

        float zp = 0.0f;
        if (tid < 32)
            zp = __ldg(zin + (size_t)ta * G4 + (tid >> 3) * HID
                       + blk * UPB + (tid & 7));

        unsigned long long acc0 = 0ull, acc1 = 0ull;
#pragma unroll
        for (int k = 0; k < 32; k += 2) {
            unsigned long long h0 = *(const unsigned long long*)(hs + 2 * (sub + 8 * k));
            unsigned long long h1 = *(const unsigned long long*)(hs + 2 * (sub + 8 * (k + 1)));
            asm("fma.rn.f32x2 %0, %1, %2, %0;" : "+l"(acc0) : "l"(wp[k]),     "l"(h0));
            asm("fma.rn.f32x2 %0, %1, %2, %0;" : "+l"(acc1) : "l"(wp[k + 1]), "l"(h1));
        }
        float ax, ay, bx, by;
        asm("mov.b64 {%0,%1}, %2;" : "=f"(ax), "=f"(ay) : "l"(acc0));
        asm("mov.b64 {%0,%1}, %2;" : "=f"(bx), "=f"(by) : "l"(acc1));
        float acc = (ax + ay) + (bx + by);
        acc += __shfl_down_sync(0xffffffffu, acc, 4, 8);
        acc += __shfl_down_sync(0xffffffffu, acc, 2, 8);
        acc += __shfl_down_sync(0xffffffffu, acc, 1, 8);
        if (sub == 0) zs[row] = acc;
        __syncthreads();

        if (tid < 32) {
            const int gate = tid >> 3;               // 0=i 1=f 2=g 3=o
            float z = zp + zs[tid];
            float arg = (gate == 2) ? z : 0.5f * z;
            float tv = tanh_f(arg);
            float val = (gate == 2) ? tv : 0.5f + 0.5f * tv;   // sigm via tanh
            float fg = __shfl_sync(0xffffffffu, val, tid + 8);
            float gg = __shfl_sync(0xffffffffu, val, tid + 16);
            float og = __shfl_sync(0xffffffffu, val, tid + 24);
            float* line = pub + ((size_t)ta * NBLK + blk) * 32;
            if (tid < 8) {
                c = fg * c + val * gg;
                float h = og * tanh_f(c);
                line[tid] = h;                       // publish h word
                hs[blk * UPB + tid] = h;             // own chunk direct to smem
            }
            __syncwarp(0xffffffffu);
            if (tid == 0)
                st_release_u32((unsigned int*)(line + 8), 1u);
        }

        if (t < LSEQ - 1) {
            int pp = tid - 64;
            if (pp >= 0 && pp < 63) {
                int peer = pp + (pp >= blk ? 1 : 0);       // skip own block
                const float* line = pub + ((size_t)ta * NBLK + peer) * 32;
                const unsigned int* fp = (const unsigned int*)(line + 8);
                while (ld_acquire_u32(fp) == 0u) { }
                uint4 a = ldcg_v4((const uint4*)line);
                uint4 b = ldcg_v4((const uint4*)line + 1);
                uint4* hd = (uint4*)(hs + peer * UPB);
                hd[0] = a; hd[1] = b;
            }
        }
        __syncthreads();
    }
}

// ---------------- pairwise scores ------------------------------------------
// scores[i][j] = sum_m tanh(mlp[i][m] + mlp[j+1][m]) * w[m] + b
// tanh(v) = 2t/(1+t^2), t = tanh(v/2) by odd deg-13 Taylor (|v|<=1.2,
// abs err <= 1.4e-6), evaluated PACKED f32x2 over m-pairs; 1 MUFU.RCP/elem.
// Chunks with any |mlp| > 0.6 (set at tile load) take the exact tanh_f path.
__global__ void __launch_bounds__(256) pair_scores(
    const float* __restrict__ ow, const float* __restrict__ obp,
    float* __restrict__ out)
{
    __shared__ __align__(16) float miT[32][66];   // [row][m] transposed-in
    __shared__ __align__(16) float mjT[32][66];
    __shared__ __align__(8)  float wch[64];       // 2*w (double-angle fold)
    __shared__ int s_oob[8];                      // per-chunk outlier flag

    const int tid = threadIdx.x;
    const int tx  = tid & 31;
    const int ty  = tid >> 5;            // 0..7
    const int i0  = blockIdx.y * 32;
    const int j0  = blockIdx.x * 32;

    if (tid < 8) s_oob[tid] = 0;

    // packed Taylor coeffs for t = v*T(v^2) = tanh(v/2)
    const u64p T0 = dup2( 0.5f);
    const u64p T1 = dup2(-4.16666666667e-2f);
    const u64p T2 = dup2( 4.16666666667e-3f);
    const u64p T3 = dup2(-4.21626984127e-4f);
    const u64p T4 = dup2( 4.27139136788e-5f);
    const u64p T5 = dup2(-4.32775274897e-6f);
    const u64p T6 = dup2( 4.38491994745e-7f);
    const u64p ONE2 = dup2(1.0f);

    u64p acc2[4] = {dup2(0.f), dup2(0.f), dup2(0.f), dup2(0.f)};
    float facc[4] = {0.f, 0.f, 0.f, 0.f};        // slow-path accumulator

    for (int ch = 0; ch < MDIM / 64; ch++) {
        const int mc = ch * 64;
        __syncthreads();                          // protect prev-iter reads
#pragma unroll
        for (int rep = 0; rep < 8; rep++) {
            int idx  = tid + rep * 256;
            int r    = idx >> 6;                  // 0..31
            int cidx = idx & 63;
            float a = g_mlp[(size_t)(i0 + r) * MDIM + mc + cidx];
            miT[r][cidx] = a;
            int jrow = j0 + r + 1;
            float b = (jrow < LSEQ)
                    ? g_mlp[(size_t)jrow * MDIM + mc + cidx] : 0.0f;
            mjT[r][cidx] = b;
            if (fabsf(a) > 0.6f || fabsf(b) > 0.6f) s_oob[ch] = 1;
        }
        if (tid < 64) wch[tid] = 2.0f * ow[mc + tid];
        __syncthreads();

        if (!s_oob[ch]) {
            // fast path: packed pairs along m
#pragma unroll 2
            for (int cc2 = 0; cc2 < 32; cc2++) {
                u64p jw  = *(const u64p*)&mjT[tx][2 * cc2];
                u64p wv2 = *(const u64p*)&wch[2 * cc2];
#pragma unroll
                for (int ii = 0; ii < 4; ii++) {
                    u64p mi = *(const u64p*)&miT[ty + 8 * ii][2 * cc2];
                    u64p v, q, p, tt, s;
                    ADD2(v, mi, jw);
                    MUL2(q, v, v);
                    FMA2(p, T6, q, T5);
                    FMA2(p, p, q, T4);
                    FMA2(p, p, q, T3);
                    FMA2(p, p, q, T2);
                    FMA2(p, p, q, T1);
                    FMA2(p, p, q, T0);
                    MUL2(tt, v, p);               // t = tanh(v/2)
                    FMA2(s, tt, tt, ONE2);        // 1 + t^2
                    float slo, shi;
                    asm("mov.b64 {%0,%1},%2;" : "=f"(slo), "=f"(shi) : "l"(s));
                    float rlo = rcp_f(slo), rhi = rcp_f(shi);
                    u64p rr;
                    asm("mov.b64 %0,{%1,%2};" : "=l"(rr) : "f"(rlo), "f"(rhi));
                    u64p tr;
                    MUL2(tr, tt, rr);             // t/(1+t^2)
                    FMA2(acc2[ii], tr, wv2, acc2[ii]);  // * (2w)
                }
            }
        } else {
            // exact path (rare): scalar tanh_f over this chunk
            for (int cc = 0; cc < 64; cc++) {
                float jv = mjT[tx][cc];
                float wv = 0.5f * wch[cc];
#pragma unroll
                for (int ii = 0; ii < 4; ii++) {
                    float v = miT[ty + 8 * ii][cc] + jv;
                    facc[ii] += tanh_f(v) * wv;
                }
            }
        }
    }

    float ob = obp[0];
    int j = j0 + tx;
    if (j < LSEQ - 1) {
#pragma unroll
        for (int ii = 0; ii < 4; ii++) {
            float lo, hi;
            asm("mov.b64 {%0,%1},%2;" : "=f"(lo), "=f"(hi) : "l"(acc2[ii]));
            int i = i0 + ty + 8 * ii;
            out[(size_t)i * (LSEQ - 1) + j] = lo + hi + facc[ii] + ob;
        }
    }
}

// ---------------- launch ----------------------------------------------------
extern "C" void kernel_launch(void* const* d_in, const int* in_sizes, int n_in,
                              void* d_out, int out_size)
{
    const int*   wi    = (const int*)  d_in[0];
    const int*   pi    = (const int*)  d_in[1];
    const float* we    = (const float*)d_in[2];
    const float* pe    = (const float*)d_in[3];
    const float* Wih0  = (const float*)d_in[4];
    const float* Whh0  = (const float*)d_in[5];
    const float* bih0  = (const float*)d_in[6];
    const float* bhh0  = (const float*)d_in[7];
    const float* Wih0r = (const float*)d_in[8];
    const float* Whh0r = (const float*)d_in[9];
    const float* bih0r = (const float*)d_in[10];
    const float* bhh0r = (const float*)d_in[11];
    const float* Wih1  = (const float*)d_in[12];
    const float* Whh1  = (const float*)d_in[13];
    const float* bih1  = (const float*)d_in[14];
    const float* bhh1  = (const float*)d_in[15];
    const float* Wih1r = (const float*)d_in[16];
    const float* Whh1r = (const float*)d_in[17];
    const float* bih1r = (const float*)d_in[18];
    const float* bhh1r = (const float*)d_in[19];
    const float* mlpW  = (const float*)d_in[20];
    const float* mlpb  = (const float*)d_in[21];
    const float* outw  = (const float*)d_in[22];
    const float* outb  = (const float*)d_in[23];

    embed_k<<<LSEQ, DIN>>>(wi, pi, we, pe);
    zero_pub_k<<<2048, 512>>>();

    // layer 0 input projections (both directions, one launch)
    gemm_tn<<<dim3(G4 / 64, LSEQ / 64, 2), 256>>>(
        0, 0, Wih0, bih0, bhh0, 3, Wih0r, bih0r, bhh0r, 4, LSEQ, G4, DIN);
    lstm_scan<<<128, 256>>>(Whh0, Whh0r, 6);

    // layer 1 input projections (A = pub1 layout)
    gemm_tn<<<dim3(G4 / 64, LSEQ / 64, 2), 256>>>(
        6, 1, Wih1, bih1, bhh1, 3, Wih1r, bih1r, bhh1r, 4, LSEQ, G4, 2 * HID);
    lstm_scan<<<128, 256>>>(Whh1, Whh1r, 7);

    // MLP projection (A = pub2 layout)
    gemm_tn<<<dim3(MDIM / 64, LSEQ / 64, 1), 256>>>(
        7, 1, mlpW, mlpb, nullptr, 5, mlpW, mlpb, nullptr, 5, LSEQ, MDIM, 2 * HID);
    // pairwise scores
    pair_scores<<<dim3(16, 16), 256>>>(outw, outb, (float*)d_out);
}

// round 14
// speedup vs baseline: 1.4296x; 1.4296x over previous
#include <cuda_runtime.h>
#include <cuda_bf16.h>

// Problem dims (fixed by the dataset)
#define LSEQ 512
#define DIN  320
#define HID  512
#define G4   2048   // 4*H
#define MDIM 512
#define NBLK 64     // blocks per direction
#define UPB  8      // hidden units per block

// ---------------- scratch (static device globals; no allocation) ----------
__device__ float g_x0 [LSEQ * DIN];        // embeddings
__device__ float g_zf [LSEQ * G4];         // input-projection, forward dir
__device__ float g_zb [LSEQ * G4];         // input-projection, backward dir
__device__ float g_mlp[LSEQ * MDIM];       // per-node MLP
__device__ float g_th [LSEQ * MDIM];       // tanh(mlp), precomputed once
// layer outputs in "publish line" layout: [dir][t][blk][32 words]
//   floats 0..7 = h chunk, word 8 = flag, rest pad (one 128B line)
__device__ __align__(128) float g_pub1[2 * LSEQ * NBLK * 32];
__device__ __align__(128) float g_pub2[2 * LSEQ * NBLK * 32];

__device__ __forceinline__ float* bufsel(int id) {
    switch (id) {
        case 0: return g_x0;
        case 3: return g_zf;
        case 4: return g_zb;
        case 5: return g_mlp;
        case 6: return g_pub1;
        default: return g_pub2;
    }
}

__device__ __forceinline__ float tanh_f(float x) {
    float a = fabsf(x);
    float e = __expf(-2.0f * a);
    float r = __fdividef(1.0f - e, 1.0f + e);
    return copysignf(r, x);
}

__device__ __forceinline__ void st_release_u32(unsigned int* p, unsigned int v) {
    asm volatile("st.release.gpu.global.u32 [%0], %1;" :: "l"(p), "r"(v) : "memory");
}
__device__ __forceinline__ unsigned int ld_acquire_u32(const unsigned int* p) {
    unsigned int v;
    asm volatile("ld.acquire.gpu.global.u32 %0, [%1];" : "=r"(v) : "l"(p) : "memory");
    return v;
}
__device__ __forceinline__ uint4 ldcg_v4(const uint4* p) {
    uint4 v;
    asm volatile("ld.global.cg.v4.u32 {%0,%1,%2,%3}, [%4];"
                 : "=r"(v.x), "=r"(v.y), "=r"(v.z), "=r"(v.w) : "l"(p) : "memory");
    return v;
}
__device__ __forceinline__ float rcp_f(float x) {
    float r; asm("rcp.approx.ftz.f32 %0,%1;" : "=f"(r) : "f"(x)); return r;
}

// ---------------- embedding gather ----------------------------------------
__global__ void embed_k(const int* __restrict__ wi, const int* __restrict__ pi,
                        const float* __restrict__ we, const float* __restrict__ pe)
{
    int t = blockIdx.x;
    int d = threadIdx.x;             // 320 threads
    float v;
    if (d < 256) v = we[(size_t)wi[t] * 256 + d];
    else         v = pe[(size_t)pi[t] * 64 + (d - 256)];
    g_x0[t * DIN + d] = v;
}

// ---------------- pub reset (every replay, before the scans) --------------
__global__ void zero_pub_k()
{
    int idx = blockIdx.x * blockDim.x + threadIdx.x;   // 2048*512 = 1048576
    uint4 z = make_uint4(0u, 0u, 0u, 0u);
    if (idx < 524288) ((uint4*)g_pub1)[idx] = z;       // each buf: 524288 uint4
    else              ((uint4*)g_pub2)[idx - 524288] = z;
}

// ---------------- tanh precompute over mlp (262144 elems) -----------------
__global__ void tanh_mlp_k()
{
    int idx = blockIdx.x * blockDim.x + threadIdx.x;
    g_th[idx] = tanh_f(g_mlp[idx]);
}

// ---------------- f32 GEMM:  C[M,N] = A[M,K] * B[N,K]^T + b1 + b2 ---------
// amode=0: A dense [M][K].  amode=1: A in pub-line layout (K=1024,
// col c -> pub[c>>9][row][(c&511)>>3][c&7]).
__global__ void __launch_bounds__(256) gemm_tn(
    int aid, int amode,
    const float* __restrict__ B0, const float* __restrict__ b1_0,
    const float* __restrict__ b2_0, int cid0,
    const float* __restrict__ B1, const float* __restrict__ b1_1,
    const float* __restrict__ b2_1, int cid1,
    int M, int N, int K)
{
    const float* A  = bufsel(aid);
    const float* B  = blockIdx.z ? B1   : B0;
    const float* b1 = blockIdx.z ? b1_1 : b1_0;
    const float* b2 = blockIdx.z ? b2_1 : b2_0;
    float*       C  = bufsel(blockIdx.z ? cid1 : cid0);

    __shared__ float As[16][65];
    __shared__ float Bs[16][65];

    const int tid = threadIdx.x;
    const int tx  = tid & 15;
    const int ty  = tid >> 4;
    const int m0  = blockIdx.y * 64;
    const int n0  = blockIdx.x * 64;

    const int lr = tid >> 2;
    const int lk = (tid & 3) * 4;

    const float* Ap = A + (size_t)(m0 + lr) * K + lk;           // amode=0 path
    const float* Aprow = A + (size_t)(m0 + lr) * (NBLK * 32);   // amode=1 path
    const float* Bp = B + (size_t)(n0 + lr) * K + lk;

    float acc[4][4] = {};

    for (int k0 = 0; k0 < K; k0 += 16) {
        float4 av;
        if (amode) {
            int c  = k0 + lk;                 // global column 0..1023
            int d  = c >> 9;                  // direction
            int cc = c & 511;
            av = *(const float4*)(Aprow + (size_t)d * (LSEQ * NBLK * 32)
                                  + (cc >> 3) * 32 + (cc & 7));
        } else {
            av = *(const float4*)(Ap + k0);
        }
        float4 bv = *(const float4*)(Bp + k0);
        __syncthreads();
        As[lk + 0][lr] = av.x; As[lk + 1][lr] = av.y;
        As[lk + 2][lr] = av.z; As[lk + 3][lr] = av.w;
        Bs[lk + 0][lr] = bv.x; Bs[lk + 1][lr] = bv.y;
        Bs[lk + 2][lr] = bv.z; Bs[lk + 3][lr] = bv.w;
        __syncthreads();
#pragma unroll
        for (int kk = 0; kk < 16; kk++) {
            float a[4], b[4];
#pragma unroll
            for (int i = 0; i < 4; i++) a[i] = As[kk][ty + 16 * i];
#pragma unroll
            for (int j = 0; j < 4; j++) b[j] = Bs[kk][tx + 16 * j];
#pragma unroll
            for (int i = 0; i < 4; i++)
#pragma unroll
                for (int j = 0; j < 4; j++)
                    acc[i][j] += a[i] * b[j];
        }
    }

#pragma unroll
    for (int j = 0; j < 4; j++) {
        int n = n0 + tx + 16 * j;
        float bb = 0.0f;
        if (b1) bb += b1[n];
        if (b2) bb += b2[n];
#pragma unroll
        for (int i = 0; i < 4; i++) {
            C[(size_t)(m0 + ty + 16 * i) * N + n] = acc[i][j] + bb;
        }
    }
}

// ---------------- persistent bidirectional LSTM scan (R8, proven) ---------
__global__ void __launch_bounds__(256, 1) lstm_scan(
    const float* __restrict__ whf, const float* __restrict__ whb, int outid)
{
    const int dir = blockIdx.x >> 6;     // 0 fwd, 1 bwd
    const int blk = blockIdx.x & 63;
    const int tid = threadIdx.x;
    const int row = tid >> 3;            // 0..31 local row
    const int sub = tid & 7;             // 8 threads per row
    const int grow = (row >> 3) * HID + blk * UPB + (row & 7);

    const float* zin = dir ? g_zb : g_zf;
    const float* Whh = dir ? whb : whf;
    float* pub = bufsel(outid) + (size_t)dir * LSEQ * NBLK * 32;

    unsigned long long wp[32];
    const unsigned long long* w2 =
        (const unsigned long long*)(Whh + (size_t)grow * HID);
#pragma unroll
    for (int k = 0; k < 32; k++) wp[k] = w2[sub + 8 * k];

    __shared__ __align__(16) float hs[HID];
    __shared__ float zs[32];
    hs[tid] = 0.0f; hs[tid + 256] = 0.0f;
    float c = 0.0f;                      // live only on lanes 0..7 of warp 0
    __syncthreads();

    for (int t = 0; t < LSEQ; t++) {
        const int ta = dir ? (LSEQ - 1 - t) : t;

        float zp = 0.0f;
        if (tid < 32)
            zp = __ldg(zin + (size_t)ta * G4 + (tid >> 3) * HID
                       + blk * UPB + (tid & 7));

        unsigned long long acc0 = 0ull, acc1 = 0ull;
#pragma unroll
        for (int k = 0; k < 32; k += 2) {
            unsigned long long h0 = *(const unsigned long long*)(hs + 2 * (sub + 8 * k));
            unsigned long long h1 = *(const unsigned long long*)(hs + 2 * (sub + 8 * (k + 1)));
            asm("fma.rn.f32x2 %0, %1, %2, %0;" : "+l"(acc0) : "l"(wp[k]),     "l"(h0));
            asm("fma.rn.f32x2 %0, %1, %2, %0;" : "+l"(acc1) : "l"(wp[k + 1]), "l"(h1));
        }
        float ax, ay, bx, by;
        asm("mov.b64 {%0,%1}, %2;" : "=f"(ax), "=f"(ay) : "l"(acc0));
        asm("mov.b64 {%0,%1}, %2;" : "=f"(bx), "=f"(by) : "l"(acc1));
        float acc = (ax + ay) + (bx + by);
        acc += __shfl_down_sync(0xffffffffu, acc, 4, 8);
        acc += __shfl_down_sync(0xffffffffu, acc, 2, 8);
        acc += __shfl_down_sync(0xffffffffu, acc, 1, 8);
        if (sub == 0) zs[row] = acc;
        __syncthreads();

        if (tid < 32) {
            const int gate = tid >> 3;               // 0=i 1=f 2=g 3=o
            float z = zp + zs[tid];
            float arg = (gate == 2) ? z : 0.5f * z;
            float tv = tanh_f(arg);
            float val = (gate == 2) ? tv : 0.5f + 0.5f * tv;   // sigm via tanh
            float fg = __shfl_sync(0xffffffffu, val, tid + 8);
            float gg = __shfl_sync(0xffffffffu, val, tid + 16);
            float og = __shfl_sync(0xffffffffu, val, tid + 24);
            float* line = pub + ((size_t)ta * NBLK + blk) * 32;
            if (tid < 8) {
                c = fg * c + val * gg;
                float h = og * tanh_f(c);
                line[tid] = h;                       // publish h word
                hs[blk * UPB + tid] = h;             // own chunk direct to smem
            }
            __syncwarp(0xffffffffu);
            if (tid == 0)
                st_release_u32((unsigned int*)(line + 8), 1u);
        }

        if (t < LSEQ - 1) {
            int pp = tid - 64;
            if (pp >= 0 && pp < 63) {
                int peer = pp + (pp >= blk ? 1 : 0);       // skip own block
                const float* line = pub + ((size_t)ta * NBLK + peer) * 32;
                const unsigned int* fp = (const unsigned int*)(line + 8);
                while (ld_acquire_u32(fp) == 0u) { }
                uint4 a = ldcg_v4((const uint4*)line);
                uint4 b = ldcg_v4((const uint4*)line + 1);
                uint4* hd = (uint4*)(hs + peer * UPB);
                hd[0] = a; hd[1] = b;
            }
        }
        __syncthreads();
    }
}

// ---------------- pairwise scores ------------------------------------------
// scores[i][j] = sum_m tanh(mlp[i][m] + mlp[j+1][m]) * w[m] + b
// EXACT tanh addition identity on precomputed ta = tanh(mlp):
//   tanh(a+b) = (ta + tb) / (1 + ta*tb)
// Inner loop: FADD, FFMA, MUFU.RCP, FMUL, FFMA  (1 MUFU/elem, no guard).
__global__ void __launch_bounds__(256) pair_scores(
    const float* __restrict__ ow, const float* __restrict__ obp,
    float* __restrict__ out)
{
    __shared__ float miT[64][33];
    __shared__ float mjT[64][33];
    __shared__ float wch[64];

    const int tid = threadIdx.x;
    const int tx  = tid & 31;
    const int ty  = tid >> 5;            // 0..7
    const int i0  = blockIdx.y * 32;
    const int j0  = blockIdx.x * 32;

    float acc[4] = {0.f, 0.f, 0.f, 0.f};

    for (int mc = 0; mc < MDIM; mc += 64) {
        __syncthreads();
#pragma unroll
        for (int rep = 0; rep < 8; rep++) {
            int idx  = tid + rep * 256;
            int r    = idx >> 6;
            int cidx = idx & 63;
            miT[cidx][r] = g_th[(size_t)(i0 + r) * MDIM + mc + cidx];
            int jrow = j0 + r + 1;
            mjT[cidx][r] = (jrow < LSEQ)
                         ? g_th[(size_t)jrow * MDIM + mc + cidx] : 0.0f;
        }
        if (tid < 64) wch[tid] = ow[mc + tid];
        __syncthreads();

#pragma unroll 4
        for (int cc = 0; cc < 64; cc++) {
            float tb = mjT[cc][tx];
            float wv = wch[cc];
#pragma unroll
            for (int ii = 0; ii < 4; ii++) {
                float ta = miT[cc][ty + 8 * ii];
                float s  = ta + tb;                  // tanh(a)+tanh(b)
                float d  = fmaf(ta, tb, 1.0f);       // 1 + tanh(a)tanh(b)
                float r  = rcp_f(d);                 // d in (0,2): safe
                float sw = s * wv;
                acc[ii]  = fmaf(sw, r, acc[ii]);
            }
        }
    }

    float ob = obp[0];
    int j = j0 + tx;
    if (j < LSEQ - 1) {
#pragma unroll
        for (int ii = 0; ii < 4; ii++) {
            int i = i0 + ty + 8 * ii;
            out[(size_t)i * (LSEQ - 1) + j] = acc[ii] + ob;
        }
    }
}

// ---------------- launch ----------------------------------------------------
extern "C" void kernel_launch(void* const* d_in, const int* in_sizes, int n_in,
                              void* d_out, int out_size)
{
    const int*   wi    = (const int*)  d_in[0];
    const int*   pi    = (const int*)  d_in[1];
    const float* we    = (const float*)d_in[2];
    const float* pe    = (const float*)d_in[3];
    const float* Wih0  = (const float*)d_in[4];
    const float* Whh0  = (const float*)d_in[5];
    const float* bih0  = (const float*)d_in[6];
    const float* bhh0  = (const float*)d_in[7];
    const float* Wih0r = (const float*)d_in[8];
    const float* Whh0r = (const float*)d_in[9];
    const float* bih0r = (const float*)d_in[10];
    const float* bhh0r = (const float*)d_in[11];
    const float* Wih1  = (const float*)d_in[12];
    const float* Whh1  = (const float*)d_in[13];
    const float* bih1  = (const float*)d_in[14];
    const float* bhh1  = (const float*)d_in[15];
    const float* Wih1r = (const float*)d_in[16];
    const float* Whh1r = (const float*)d_in[17];
    const float* bih1r = (const float*)d_in[18];
    const float* bhh1r = (const float*)d_in[19];
    const float* mlpW  = (const float*)d_in[20];
    const float* mlpb  = (const float*)d_in[21];
    const float* outw  = (const float*)d_in[22];
    const float* outb  = (const float*)d_in[23];

    embed_k<<<LSEQ, DIN>>>(wi, pi, we, pe);
    zero_pub_k<<<2048, 512>>>();

    // layer 0 input projections (both directions, one launch)
    gemm_tn<<<dim3(G4 / 64, LSEQ / 64, 2), 256>>>(
        0, 0, Wih0, bih0, bhh0, 3, Wih0r, bih0r, bhh0r, 4, LSEQ, G4, DIN);
    lstm_scan<<<128, 256>>>(Whh0, Whh0r, 6);

    // layer 1 input projections (A = pub1 layout)
    gemm_tn<<<dim3(G4 / 64, LSEQ / 64, 2), 256>>>(
        6, 1, Wih1, bih1, bhh1, 3, Wih1r, bih1r, bhh1r, 4, LSEQ, G4, 2 * HID);
    lstm_scan<<<128, 256>>>(Whh1, Whh1r, 7);

    // MLP projection (A = pub2 layout)
    gemm_tn<<<dim3(MDIM / 64, LSEQ / 64, 1), 256>>>(
        7, 1, mlpW, mlpb, nullptr, 5, mlpW, mlpb, nullptr, 5, LSEQ, MDIM, 2 * HID);
    // tanh precompute, then pairwise scores via addition identity
    tanh_mlp_k<<<512, 512>>>();
    pair_scores<<<dim3(16, 16), 256>>>(outw, outb, (float*)d_out);
}